// round 3
// baseline (speedup 1.0000x reference)
#include <cuda_runtime.h>
#include <stdint.h>

// Problem constants (shapes fixed by the dataset)
#define NN 100000
#define EE 3200000
#define DD 128     // input feature dim
#define F1 64      // hidden dim

// ---------------- device scratch (no allocation allowed) ----------------
__device__ int   g_is64;
__device__ int   g_src[EE];
__device__ int   g_dst[EE];
__device__ int   g_deg[NN];
__device__ float g_dinv[NN];
__device__ __align__(16) float g_g1 [NN * F1];   // dinv[v] * (x[v] @ W1)
__device__ __align__(16) float g_acc1[NN * F1];  // aggregation accumulator L1
__device__ float g_g2 [NN];                      // dinv[v] * (h[v] @ W2)
__device__ float g_acc2[NN];                     // aggregation accumulator L2

// vector reduction into global memory (sm_90+ PTX)
__device__ __forceinline__ void red_add_f4(float* p, float4 v) {
    asm volatile("red.global.add.v4.f32 [%0], {%1,%2,%3,%4};"
                 :: "l"(p), "f"(v.x), "f"(v.y), "f"(v.z), "f"(v.w)
                 : "memory");
}

// ---------------- K0: detect int64 vs int32 edge indices ----------------
// int64 little-endian: every odd 32-bit word is the (zero) high half.
__global__ void k_detect(const int* __restrict__ ew) {
    __shared__ int any;
    if (threadIdx.x == 0) any = 0;
    __syncthreads();
    int local = 0;
    for (int i = 1 + 2 * threadIdx.x; i < 4096; i += 2 * blockDim.x)
        if (ew[i] != 0) local = 1;
    if (local) atomicOr(&any, 1);
    __syncthreads();
    if (threadIdx.x == 0) g_is64 = (any == 0);
}

// ---------------- K1: normalize edges to int32 src/dst ----------------
__global__ void k_convert(const void* __restrict__ e, int E) {
    int i = blockIdx.x * blockDim.x + threadIdx.x;
    if (i >= E) return;
    if (g_is64) {
        const long long* p = (const long long*)e;
        g_src[i] = (int)p[i];
        g_dst[i] = (int)p[(long long)E + i];
    } else {
        const int* p = (const int*)e;
        g_src[i] = p[i];
        g_dst[i] = p[E + i];
    }
}

// ---------------- K2: degree (init 1 for self-loop, count dst) ----------------
__global__ void k_deginit(int N) {
    int v = blockIdx.x * blockDim.x + threadIdx.x;
    if (v < N) g_deg[v] = 1;
}
__global__ void k_count(int E) {
    int i = blockIdx.x * blockDim.x + threadIdx.x;
    if (i < E) atomicAdd(&g_deg[g_dst[i]], 1);
}
__global__ void k_dinv(int N) {
    int v = blockIdx.x * blockDim.x + threadIdx.x;
    if (v < N) g_dinv[v] = rsqrtf((float)g_deg[v]);
}

// ---------------- K3: g1 = dinv * (x @ W1); acc1 = g1 (self-loop init) ----------------
// 32 nodes per block, 256 threads. smem: W1 (32KB) + x tile (16KB) = 48KB.
// Thread (np, jq): nodes {2np, 2np+1}, features [4jq, 4jq+4).
__global__ void k_gemm(const float* __restrict__ x, const float* __restrict__ W1, int N) {
    __shared__ float ws[DD * F1];   // 32768 B
    __shared__ float xs[32 * DD];   // 16384 B
    int t = threadIdx.x;
    int base = blockIdx.x * 32;

    for (int i = t; i < DD * F1 / 4; i += 256)
        ((float4*)ws)[i] = ((const float4*)W1)[i];
    for (int i = t; i < 32 * DD / 4; i += 256) {
        int row = i >> 5, col = i & 31;
        float4 v = make_float4(0.f, 0.f, 0.f, 0.f);
        if (base + row < N) v = ((const float4*)x)[(size_t)(base + row) * 32 + col];
        ((float4*)xs)[i] = v;
    }
    __syncthreads();

    int jq = t & 15;
    int np = t >> 4;
    float4 a0 = make_float4(0.f, 0.f, 0.f, 0.f);
    float4 a1 = make_float4(0.f, 0.f, 0.f, 0.f);
    const float* xr0 = &xs[(2 * np) * DD];
    const float* xr1 = &xs[(2 * np + 1) * DD];

    #pragma unroll 4
    for (int k = 0; k < DD; k++) {
        float4 w = ((const float4*)ws)[k * 16 + jq];
        float x0 = xr0[k], x1 = xr1[k];
        a0.x = fmaf(x0, w.x, a0.x); a0.y = fmaf(x0, w.y, a0.y);
        a0.z = fmaf(x0, w.z, a0.z); a0.w = fmaf(x0, w.w, a0.w);
        a1.x = fmaf(x1, w.x, a1.x); a1.y = fmaf(x1, w.y, a1.y);
        a1.z = fmaf(x1, w.z, a1.z); a1.w = fmaf(x1, w.w, a1.w);
    }

    int n0 = base + 2 * np;
    int n1 = n0 + 1;
    if (n0 < N) {
        float dv = g_dinv[n0];
        float4 o = make_float4(a0.x * dv, a0.y * dv, a0.z * dv, a0.w * dv);
        ((float4*)g_g1)[n0 * 16 + jq] = o;
        ((float4*)g_acc1)[n0 * 16 + jq] = o;
    }
    if (n1 < N) {
        float dv = g_dinv[n1];
        float4 o = make_float4(a1.x * dv, a1.y * dv, a1.z * dv, a1.w * dv);
        ((float4*)g_g1)[n1 * 16 + jq] = o;
        ((float4*)g_acc1)[n1 * 16 + jq] = o;
    }
}

// ---------------- K4: edge scatter layer 1 (64-wide, float4 red-adds) ----------------
// 16 threads per edge, one float4 each. Half-warp gathers a coalesced 256B row.
__global__ void k_scatter1(int E) {
    int t = blockIdx.x * blockDim.x + threadIdx.x;
    if (t >= E * 16) return;
    int e = t >> 4, c = t & 15;
    int s = g_src[e];
    int d = g_dst[e];
    float4 v = ((const float4*)g_g1)[s * 16 + c];
    red_add_f4(&g_acc1[d * 64 + c * 4], v);
}

// ---------------- K5: fused epilogue1 + projection2 ----------------
// warp per node: h = relu(dinv*acc1 + b1); z = dinv * (h . W2); acc2 init = z.
__global__ void k_fuse(const float* __restrict__ b1, const float* __restrict__ W2, int N) {
    int w = (blockIdx.x * blockDim.x + threadIdx.x) >> 5;
    int lane = threadIdx.x & 31;
    if (w >= N) return;
    float dv = g_dinv[w];
    float a0 = g_acc1[w * 64 + lane];
    float a1 = g_acc1[w * 64 + 32 + lane];
    float h0 = fmaxf(fmaf(dv, a0, __ldg(&b1[lane])), 0.f);
    float h1 = fmaxf(fmaf(dv, a1, __ldg(&b1[32 + lane])), 0.f);
    float p = h0 * __ldg(&W2[lane]) + h1 * __ldg(&W2[32 + lane]);
    #pragma unroll
    for (int o = 16; o > 0; o >>= 1) p += __shfl_xor_sync(0xffffffffu, p, o);
    if (lane == 0) {
        float z = dv * p;
        g_g2[w] = z;
        g_acc2[w] = z;   // self-loop
    }
}

// ---------------- K6: edge scatter layer 2 (scalar) ----------------
__global__ void k_scatter2(int E) {
    int i = blockIdx.x * blockDim.x + threadIdx.x;
    if (i >= E) return;
    atomicAdd(&g_acc2[g_dst[i]], g_g2[g_src[i]]);
}

// ---------------- K7: final output ----------------
__global__ void k_final(const float* __restrict__ b2, float* __restrict__ out, int N) {
    int v = blockIdx.x * blockDim.x + threadIdx.x;
    if (v < N) out[v] = fmaf(g_dinv[v], g_acc2[v], __ldg(&b2[0]));
}

// ---------------- launch ----------------
extern "C" void kernel_launch(void* const* d_in, const int* in_sizes, int n_in,
                              void* d_out, int out_size) {
    const float* x  = (const float*)d_in[0];
    const void*  e  = d_in[1];
    const float* W1 = (const float*)d_in[2];
    const float* b1 = (const float*)d_in[3];
    const float* W2 = (const float*)d_in[4];
    const float* b2 = (const float*)d_in[5];
    float* out = (float*)d_out;

    int N = in_sizes[0] / DD;   // 100000
    int E = in_sizes[1] / 2;    // 3200000

    k_detect  <<<1, 256>>>((const int*)e);
    k_deginit <<<(N + 255) / 256, 256>>>(N);
    k_convert <<<(E + 255) / 256, 256>>>(e, E);
    k_count   <<<(E + 255) / 256, 256>>>(E);
    k_dinv    <<<(N + 255) / 256, 256>>>(N);
    k_gemm    <<<(N + 31) / 32, 256>>>(x, W1, N);
    k_scatter1<<<(E * 16 + 255) / 256, 256>>>(E);
    k_fuse    <<<(N + 7) / 8, 256>>>(b1, W2, N);
    k_scatter2<<<(E + 255) / 256, 256>>>(E);
    k_final   <<<(N + 255) / 256, 256>>>(b2, out, N);
}

// round 5
// speedup vs baseline: 1.3890x; 1.3890x over previous
#include <cuda_runtime.h>
#include <stdint.h>

// Problem constants (shapes fixed by the dataset)
#define NN 100000
#define EE 3200000
#define DD 128     // input feature dim
#define F1 64      // hidden dim
#define SCAN_B 512 // scan block size (2^9)

// ---------------- device scratch (no allocation allowed) ----------------
__device__ int   g_is64;
__device__ int   g_cnt[NN];         // in-degree (real edges only)
__device__ int   g_off[NN];         // per-block-local exclusive prefix
__device__ int   g_bsum[256];       // scan block sums
__device__ int   g_rowptr[NN + 1];  // CSR row pointers (dst-major)
__device__ int   g_cursor[NN];      // fill cursors
__device__ int   g_csr[EE];         // CSR src indices
__device__ float g_dinv[NN];
__device__ __align__(16) float g_g1[NN * F1];  // dinv[v] * (x[v] @ W1)
__device__ float g_g2[NN];                     // dinv[v] * (h[v] @ W2)

// ---------------- edge decode (int64 vs int32, runtime-detected) ----------------
__device__ __forceinline__ void load_edge(const void* __restrict__ e, int E, int i,
                                          int& s, int& d) {
    if (g_is64) {
        const long long* p = (const long long*)e;
        s = (int)p[i];
        d = (int)p[(long long)E + i];
    } else {
        const int* p = (const int*)e;
        s = p[i];
        d = p[E + i];
    }
}

// ---------------- K0: detect int64 vs int32 edge indices ----------------
__global__ void k_detect(const int* __restrict__ ew) {
    __shared__ int any;
    if (threadIdx.x == 0) any = 0;
    __syncthreads();
    int local = 0;
    for (int i = 1 + 2 * threadIdx.x; i < 4096; i += 2 * blockDim.x)
        if (ew[i] != 0) local = 1;
    if (local) atomicOr(&any, 1);
    __syncthreads();
    if (threadIdx.x == 0) g_is64 = (any == 0);
}

// ---------------- K1: zero the in-degree counters ----------------
__global__ void k_zero(int N) {
    int v = blockIdx.x * blockDim.x + threadIdx.x;
    if (v < N) g_cnt[v] = 0;
}

// ---------------- K2: count in-degrees ----------------
__global__ void k_count(const void* __restrict__ e, int E) {
    int i = blockIdx.x * blockDim.x + threadIdx.x;
    if (i >= E) return;
    int s, d;
    load_edge(e, E, i, s, d);
    atomicAdd(&g_cnt[d], 1);
}

// ---------------- K3a/b/c: exclusive prefix scan of g_cnt -> rowptr ----------------
__global__ void k_scan1(int N) {
    __shared__ int sm[SCAN_B];
    int v = blockIdx.x * SCAN_B + threadIdx.x;
    int c = (v < N) ? g_cnt[v] : 0;
    sm[threadIdx.x] = c;
    __syncthreads();
    int val = c;
    for (int o = 1; o < SCAN_B; o <<= 1) {
        int t = (threadIdx.x >= o) ? sm[threadIdx.x - o] : 0;
        __syncthreads();
        val += t;
        sm[threadIdx.x] = val;
        __syncthreads();
    }
    if (v < N) g_off[v] = val - c;                      // exclusive
    if (threadIdx.x == SCAN_B - 1) g_bsum[blockIdx.x] = val;
}
__global__ void k_scan2(int nb) {
    if (threadIdx.x == 0) {
        int run = 0;
        for (int b = 0; b < nb; b++) { int t = g_bsum[b]; g_bsum[b] = run; run += t; }
    }
}
__global__ void k_scan3(int N, int E) {
    int v = blockIdx.x * blockDim.x + threadIdx.x;
    if (v < N) {
        int rp = g_off[v] + g_bsum[v >> 9];
        g_rowptr[v] = rp;
        g_cursor[v] = rp;
        g_dinv[v]   = rsqrtf((float)(g_cnt[v] + 1));    // +1 self-loop
    }
    if (v == N) g_rowptr[N] = E;
}

// ---------------- K4: CSR fill (src index per dst slot) ----------------
__global__ void k_fill(const void* __restrict__ e, int E) {
    int i = blockIdx.x * blockDim.x + threadIdx.x;
    if (i >= E) return;
    int s, d;
    load_edge(e, E, i, s, d);
    int p = atomicAdd(&g_cursor[d], 1);
    g_csr[p] = s;
}

// ---------------- K5: g1 = dinv * (x @ W1) ----------------
// 32 nodes per block, 256 threads. smem: W1 (32KB) + x tile (16KB) = 48KB.
__global__ void k_gemm(const float* __restrict__ x, const float* __restrict__ W1, int N) {
    __shared__ float ws[DD * F1];
    __shared__ float xs[32 * DD];
    int t = threadIdx.x;
    int base = blockIdx.x * 32;

    for (int i = t; i < DD * F1 / 4; i += 256)
        ((float4*)ws)[i] = ((const float4*)W1)[i];
    for (int i = t; i < 32 * DD / 4; i += 256) {
        int row = i >> 5, col = i & 31;
        float4 v = make_float4(0.f, 0.f, 0.f, 0.f);
        if (base + row < N) v = ((const float4*)x)[(size_t)(base + row) * 32 + col];
        ((float4*)xs)[i] = v;
    }
    __syncthreads();

    int jq = t & 15;
    int np = t >> 4;
    float4 a0 = make_float4(0.f, 0.f, 0.f, 0.f);
    float4 a1 = make_float4(0.f, 0.f, 0.f, 0.f);
    const float* xr0 = &xs[(2 * np) * DD];
    const float* xr1 = &xs[(2 * np + 1) * DD];

    #pragma unroll 4
    for (int k = 0; k < DD; k++) {
        float4 w = ((const float4*)ws)[k * 16 + jq];
        float x0 = xr0[k], x1 = xr1[k];
        a0.x = fmaf(x0, w.x, a0.x); a0.y = fmaf(x0, w.y, a0.y);
        a0.z = fmaf(x0, w.z, a0.z); a0.w = fmaf(x0, w.w, a0.w);
        a1.x = fmaf(x1, w.x, a1.x); a1.y = fmaf(x1, w.y, a1.y);
        a1.z = fmaf(x1, w.z, a1.z); a1.w = fmaf(x1, w.w, a1.w);
    }

    int n0 = base + 2 * np, n1 = n0 + 1;
    if (n0 < N) {
        float dv = g_dinv[n0];
        ((float4*)g_g1)[n0 * 16 + jq] =
            make_float4(a0.x * dv, a0.y * dv, a0.z * dv, a0.w * dv);
    }
    if (n1 < N) {
        float dv = g_dinv[n1];
        ((float4*)g_g1)[n1 * 16 + jq] =
            make_float4(a1.x * dv, a1.y * dv, a1.z * dv, a1.w * dv);
    }
}

// ---------------- K6: CSR gather layer 1 + epilogue + W2 projection (fused) ----------------
// Warp per node. Lane holds float2 column [2*lane, 2*lane+2) of the 64-wide row.
// Per edge the warp reads one coalesced 256B row of g1. No atomics, no acc array.
__global__ void __launch_bounds__(256, 8)
k_agg1(const float* __restrict__ b1, const float* __restrict__ W2, int N) {
    int w = (blockIdx.x * blockDim.x + threadIdx.x) >> 5;
    int lane = threadIdx.x & 31;
    if (w >= N) return;

    const float2* __restrict__ g1v = (const float2*)g_g1;
    float2 acc = __ldg(&g1v[w * 32 + lane]);             // self-loop term
    int beg = g_rowptr[w], end = g_rowptr[w + 1];

    for (int base = beg; base < end; base += 32) {
        int idx = base + lane;
        int s = (idx < end) ? __ldg(&g_csr[idx]) : 0;
        int cnt = end - base;                            // uniform across warp
        if (cnt >= 32) {
            #pragma unroll
            for (int k = 0; k < 32; k++) {
                int ss = __shfl_sync(0xffffffffu, s, k);
                float2 v = __ldg(&g1v[ss * 32 + lane]);
                acc.x += v.x; acc.y += v.y;
            }
        } else {
            for (int k = 0; k < cnt; k++) {
                int ss = __shfl_sync(0xffffffffu, s, k);
                float2 v = __ldg(&g1v[ss * 32 + lane]);
                acc.x += v.x; acc.y += v.y;
            }
        }
    }

    // epilogue: h = relu(dinv*acc + b1); z = dinv * (h . W2)
    float dv = g_dinv[w];
    float2 bb = __ldg(&((const float2*)b1)[lane]);
    float2 ww = __ldg(&((const float2*)W2)[lane]);
    float h0 = fmaxf(fmaf(dv, acc.x, bb.x), 0.f);
    float h1 = fmaxf(fmaf(dv, acc.y, bb.y), 0.f);
    float p = h0 * ww.x + h1 * ww.y;
    #pragma unroll
    for (int o = 16; o > 0; o >>= 1) p += __shfl_xor_sync(0xffffffffu, p, o);
    if (lane == 0) g_g2[w] = dv * p;
}

// ---------------- K7: CSR gather layer 2 + final bias (fused) ----------------
__global__ void k_agg2(const float* __restrict__ b2, float* __restrict__ out, int N) {
    int v = blockIdx.x * blockDim.x + threadIdx.x;
    if (v >= N) return;
    int beg = g_rowptr[v], end = g_rowptr[v + 1];
    float s0 = __ldg(&g_g2[v]), s1 = 0.f, s2 = 0.f, s3 = 0.f;  // self-loop + MLP=4
    int i = beg;
    for (; i + 4 <= end; i += 4) {
        int i0 = __ldg(&g_csr[i]);
        int i1 = __ldg(&g_csr[i + 1]);
        int i2 = __ldg(&g_csr[i + 2]);
        int i3 = __ldg(&g_csr[i + 3]);
        s0 += __ldg(&g_g2[i0]);
        s1 += __ldg(&g_g2[i1]);
        s2 += __ldg(&g_g2[i2]);
        s3 += __ldg(&g_g2[i3]);
    }
    for (; i < end; i++) s0 += __ldg(&g_g2[__ldg(&g_csr[i])]);
    out[v] = fmaf(g_dinv[v], (s0 + s1) + (s2 + s3), __ldg(b2));
}

// ---------------- launch ----------------
extern "C" void kernel_launch(void* const* d_in, const int* in_sizes, int n_in,
                              void* d_out, int out_size) {
    const float* x  = (const float*)d_in[0];
    const void*  e  = d_in[1];
    const float* W1 = (const float*)d_in[2];
    const float* b1 = (const float*)d_in[3];
    const float* W2 = (const float*)d_in[4];
    const float* b2 = (const float*)d_in[5];
    float* out = (float*)d_out;

    int N = in_sizes[0] / DD;   // 100000
    int E = in_sizes[1] / 2;    // 3200000
    int nb = (N + SCAN_B - 1) / SCAN_B;

    k_detect<<<1, 256>>>((const int*)e);
    k_zero  <<<(N + 255) / 256, 256>>>(N);
    k_count <<<(E + 255) / 256, 256>>>(e, E);
    k_scan1 <<<nb, SCAN_B>>>(N);
    k_scan2 <<<1, 32>>>(nb);
    k_scan3 <<<(N + 256) / 256, 256>>>(N, E);
    k_gemm  <<<(N + 31) / 32, 256>>>(x, W1, N);
    k_fill  <<<(E + 255) / 256, 256>>>(e, E);
    k_agg1  <<<(N * 32 + 255) / 256, 256>>>(b1, W2, N);
    k_agg2  <<<(N + 255) / 256, 256>>>(b2, out, N);
}